// round 4
// baseline (speedup 1.0000x reference)
#include <cuda_runtime.h>

#define F_DIM 513
#define T_DIM 256
#define C_DIM 8
#define N_DIM 4
#define TSPLIT 7
#define TF (T_DIM * F_DIM)        // 131328
#define NF (N_DIM * F_DIM)        // 2052
#define DIAG_LOAD 7.0710678118654755e-4f  // 0.001/sqrt(2)

// Partial Hermitian covariances: [input(2)][n(4)][chunk(7)][entry(64)][f(513)]
// entry 0..7 = diag (real), 8..35 = off-diag re (kk order), 36..63 = off-diag im
__device__ float g_partial[2 * N_DIM * TSPLIT * 64 * F_DIM];
// conj(W): [n][c][{re,im}][f]
__device__ float g_wc[N_DIM * C_DIM * 2 * F_DIM];

// t-chunk boundaries for TSPLIT=7: sizes 37,37,37,37,36,36,36
__device__ __forceinline__ int chunk_start(int y) { return y * 36 + min(y, 4); }

// -------------------------------------------------------------------------
// Pass 1: partial covariance, 4-way entry split.
// h=0: 8 diag + pairs kk 0..3   (16 accs)
// h=1: pairs kk 4..11           (16 accs)
// h=2: pairs kk 12..19          (16 accs, channels 1..7)
// h=3: pairs kk 20..27          (16 accs, channels 3..7)
// 2-t load batching for MLP=32 per thread. Block (128 f, 4 h) = 512 thr,
// <=64 regs -> 2 blocks/SM. grid (5, 7, 8) = 280 blocks.
// -------------------------------------------------------------------------
template <int H>
__device__ __forceinline__ void cov_step(
    const float xr[8], const float xi[8], float* __restrict__ acc)
{
    constexpr int KK0 = (H == 0) ? 0 : (H == 1) ? 4 : (H == 2) ? 12 : 20;
    constexpr int KK1 = (H == 0) ? 4 : (H == 1) ? 12 : (H == 2) ? 20 : 28;
    if (H == 0) {
#pragma unroll
        for (int i = 0; i < 8; i++)
            acc[i] = fmaf(xr[i], xr[i], fmaf(xi[i], xi[i], acc[i]));
    }
#pragma unroll
    for (int i = 0; i < 8; i++)
#pragma unroll
        for (int j = i + 1; j < 8; j++) {
            int kk = 7 * i - (i * (i - 1)) / 2 + (j - i - 1);
            if (kk >= KK0 && kk < KK1) {
                int l = (H == 0 ? 8 : 0) + 2 * (kk - KK0);
                acc[l]     = fmaf(xr[i], xr[j], fmaf(xi[i], xi[j], acc[l]));
                acc[l + 1] = fmaf(xi[i], xr[j], fmaf(-xr[i], xi[j], acc[l + 1]));
            }
        }
}

template <int H>
__device__ __forceinline__ void cov_body(
    const float* __restrict__ baseR, const float* __restrict__ baseI,
    int t0, int t1, float* __restrict__ dst, bool valid)
{
    constexpr int KK0  = (H == 0) ? 0 : (H == 1) ? 4 : (H == 2) ? 12 : 20;
    constexpr int KK1  = (H == 0) ? 4 : (H == 1) ? 12 : (H == 2) ? 20 : 28;
    constexpr int CMIN = (H == 3) ? 3 : (H == 2) ? 1 : 0;
    constexpr int NA   = (H == 0 ? 8 : 0) + 2 * (KK1 - KK0);  // = 16

    float acc[NA];
#pragma unroll
    for (int a = 0; a < NA; a++) acc[a] = 0.f;

    int t = t0;
    for (; t + 2 <= t1; t += 2) {
        float xr0[8] = {0}, xi0[8] = {0}, xr1[8] = {0}, xi1[8] = {0};
        int off0 = t * F_DIM, off1 = (t + 1) * F_DIM;
#pragma unroll
        for (int c = CMIN; c < 8; c++) {
            xr0[c] = __ldg(baseR + (size_t)c * TF + off0);
            xi0[c] = __ldg(baseI + (size_t)c * TF + off0);
            xr1[c] = __ldg(baseR + (size_t)c * TF + off1);
            xi1[c] = __ldg(baseI + (size_t)c * TF + off1);
        }
        cov_step<H>(xr0, xi0, acc);
        cov_step<H>(xr1, xi1, acc);
    }
    if (t < t1) {
        float xr0[8] = {0}, xi0[8] = {0};
        int off0 = t * F_DIM;
#pragma unroll
        for (int c = CMIN; c < 8; c++) {
            xr0[c] = __ldg(baseR + (size_t)c * TF + off0);
            xi0[c] = __ldg(baseI + (size_t)c * TF + off0);
        }
        cov_step<H>(xr0, xi0, acc);
    }

    if (!valid) return;
#pragma unroll
    for (int a = 0; a < NA; a++) {
        int e;
        if (H == 0 && a < 8) e = a;
        else {
            int l  = a - (H == 0 ? 8 : 0);
            int kk = KK0 + (l >> 1);
            e = ((l & 1) == 0) ? (8 + kk) : (36 + kk);
        }
        dst[(size_t)e * F_DIM] = acc[a];
    }
}

__global__ __launch_bounds__(512, 2) void cov_partial_kernel(
    const float* __restrict__ target, const float* __restrict__ noise)
{
    int fLocal = threadIdx.x;           // 0..127
    int h = threadIdx.y;                // 0..3 entry quarter
    int f  = blockIdx.x * 128 + fLocal;
    int fc = min(f, F_DIM - 1);
    int inp = blockIdx.z & 1;
    int n   = blockIdx.z >> 1;
    const float* src = inp ? noise : target;
    int t0 = chunk_start(blockIdx.y);
    int t1 = chunk_start(blockIdx.y + 1);

    const float* baseR = src + (size_t)(16 * n) * TF + fc;
    const float* baseI = src + (size_t)(16 * n + 8) * TF + fc;
    float* dst = g_partial +
        (size_t)((inp * N_DIM + n) * TSPLIT + blockIdx.y) * 64 * F_DIM + f;
    bool valid = (f < F_DIM);

    switch (h) {
        case 0: cov_body<0>(baseR, baseI, t0, t1, dst, valid); break;
        case 1: cov_body<1>(baseR, baseI, t0, t1, dst, valid); break;
        case 2: cov_body<2>(baseR, baseI, t0, t1, dst, valid); break;
        default: cov_body<3>(baseR, baseI, t0, t1, dst, valid); break;
    }
}

// -------------------------------------------------------------------------
// Pass 2: per-(n,f) solve. Block = 256 thr = 32 matrices.
// -------------------------------------------------------------------------
__global__ __launch_bounds__(256) void solve_kernel(const int* __restrict__ ref_idx)
{
    __shared__ float s_cov[2][64][33];   // [input][entry][matrix + pad]
    int tid = threadIdx.x;
    int m0  = blockIdx.x * 32;
    const float invT = 1.0f / (float)T_DIM;

#pragma unroll
    for (int r = 0; r < 16; r++) {
        int o  = r * 256 + tid;
        int mi = o & 31;
        int e  = (o >> 5) & 63;
        int ip = o >> 11;
        int m  = min(m0 + mi, NF - 1);
        int n  = m / F_DIM, f = m % F_DIM;
        const float* base = g_partial +
            (size_t)((ip * N_DIM + n) * TSPLIT) * 64 * F_DIM +
            (size_t)e * F_DIM + f;
        float sv = 0.f;
#pragma unroll
        for (int ch = 0; ch < TSPLIT; ch++)
            sv += base[(size_t)ch * 64 * F_DIM];
        s_cov[ip][e][mi] = sv * invT;
    }
    __syncthreads();

    int mi = tid >> 3;
    int i  = tid & 7;
    int m  = min(m0 + mi, NF - 1);
    int n  = m / F_DIM, f = m % F_DIM;
    const unsigned FULL = 0xffffffffu;

    float nr[8], ni[8];
#pragma unroll
    for (int j = 0; j < 8; j++) {
        if (j == i) { nr[j] = s_cov[1][i][mi] + DIAG_LOAD; ni[j] = DIAG_LOAD; }
        else {
            int a = min(i, j), b = max(i, j);
            int kk = 7 * a - (a * (a - 1)) / 2 + (b - a - 1);
            float sign = (i < j) ? 1.f : -1.f;
            nr[j] = s_cov[1][8 + kk][mi];
            ni[j] = sign * s_cov[1][36 + kk][mi];
        }
    }

#pragma unroll
    for (int kp = 0; kp < 8; kp++) {
        float akk_r = __shfl_sync(FULL, nr[kp], kp, 8);
        float akk_i = __shfl_sync(FULL, ni[kp], kp, 8);
        float idn = 1.0f / fmaf(akk_r, akk_r, akk_i * akk_i);
        float p_r = akk_r * idn, p_i = -akk_i * idn;
        float s_r[8], s_i[8];
#pragma unroll
        for (int j = 0; j < 8; j++) {
            float ar = __shfl_sync(FULL, nr[j], kp, 8);
            float ai = __shfl_sync(FULL, ni[j], kp, 8);
            s_r[j] = ar * p_r - ai * p_i;
            s_i[j] = ar * p_i + ai * p_r;
        }
        if (i == kp) {
#pragma unroll
            for (int j = 0; j < 8; j++) { nr[j] = s_r[j]; ni[j] = s_i[j]; }
            nr[kp] = p_r; ni[kp] = p_i;
        } else {
            float f_r = nr[kp], f_i = ni[kp];
#pragma unroll
            for (int j = 0; j < 8; j++) {
                if (j == kp) continue;
                nr[j] -= f_r * s_r[j] - f_i * s_i[j];
                ni[j] -= f_r * s_i[j] + f_i * s_r[j];
            }
            nr[kp] = -(f_r * p_r - f_i * p_i);
            ni[kp] = -(f_r * p_i + f_i * p_r);
        }
    }

    float tr_[8], ti[8];
#pragma unroll
    for (int j = 0; j < 8; j++) {
        if (j == i) { tr_[j] = s_cov[0][i][mi]; ti[j] = 0.f; }
        else {
            int a = min(i, j), b = max(i, j);
            int kk = 7 * a - (a * (a - 1)) / 2 + (b - a - 1);
            float sign = (i < j) ? 1.f : -1.f;
            tr_[j] = s_cov[0][8 + kk][mi];
            ti[j]  = sign * s_cov[0][36 + kk][mi];
        }
    }

    float trc_r = 0.f, trc_i = 0.f;
#pragma unroll
    for (int j = 0; j < 8; j++) {
        trc_r += nr[j] * tr_[j] + ni[j] * ti[j];
        trc_i += ni[j] * tr_[j] - nr[j] * ti[j];
    }
#pragma unroll
    for (int off = 4; off > 0; off >>= 1) {
        trc_r += __shfl_xor_sync(FULL, trc_r, off, 8);
        trc_i += __shfl_xor_sync(FULL, trc_i, off, 8);
    }

    int ref = *ref_idx;
    float pr = 0.f, pi = 0.f;
#pragma unroll
    for (int jj = 0; jj < 8; jj++)
        if (jj == ref) { pr = tr_[jj]; pi = ti[jj]; }

    float w_r = 0.f, w_i = 0.f;
#pragma unroll
    for (int j = 0; j < 8; j++) {
        float br = __shfl_sync(FULL, pr, j, 8);
        float bi = __shfl_sync(FULL, pi, j, 8);
        w_r += nr[j] * br - ni[j] * bi;
        w_i += nr[j] * bi + ni[j] * br;
    }

    float ldn = 1.0f / fmaf(trc_r, trc_r, trc_i * trc_i);
    float lr = trc_r * ldn, li = -trc_i * ldn;
    float Wr = w_r * lr - w_i * li;
    float Wi = w_r * li + w_i * lr;

    g_wc[((n * 8 + i) * 2 + 0) * F_DIM + f] = Wr;
    g_wc[((n * 8 + i) * 2 + 1) * F_DIM + f] = -Wi;
}

// -------------------------------------------------------------------------
// Pass 3: beamform, loads for both t's hoisted ahead of FMAs (MLP=32).
// grid (5, 128, 4) = 2560 blocks of 128.
// -------------------------------------------------------------------------
#define TPER 2
__global__ __launch_bounds__(128) void beamform_kernel(
    const float* __restrict__ mix, float* __restrict__ out)
{
    int f = blockIdx.x * blockDim.x + threadIdx.x;
    if (f >= F_DIM) return;
    int n  = blockIdx.z;
    int t0 = blockIdx.y * TPER;

    float wr[8], wi[8];
#pragma unroll
    for (int c = 0; c < 8; c++) {
        wr[c] = g_wc[((n * 8 + c) * 2 + 0) * F_DIM + f];
        wi[c] = g_wc[((n * 8 + c) * 2 + 1) * F_DIM + f];
    }

    const float* baseR = mix + (size_t)(16 * n) * TF + f;
    const float* baseI = mix + (size_t)(16 * n + 8) * TF + f;
    float* outR = out + (size_t)(2 * n) * TF + f;      // (N,2,1,T,F)
    float* outI = out + (size_t)(2 * n + 1) * TF + f;

    float yr[TPER][8], yi[TPER][8];
#pragma unroll
    for (int dt = 0; dt < TPER; dt++) {
        int off = (t0 + dt) * F_DIM;
#pragma unroll
        for (int c = 0; c < 8; c++) {
            yr[dt][c] = __ldg(baseR + (size_t)c * TF + off);
            yi[dt][c] = __ldg(baseI + (size_t)c * TF + off);
        }
    }
#pragma unroll
    for (int dt = 0; dt < TPER; dt++) {
        float Xr = 0.f, Xi = 0.f;
#pragma unroll
        for (int c = 0; c < 8; c++) {
            Xr += wr[c] * yr[dt][c] - wi[c] * yi[dt][c];
            Xi += wr[c] * yi[dt][c] + wi[c] * yr[dt][c];
        }
        int off = (t0 + dt) * F_DIM;
        outR[off] = Xr;
        outI[off] = Xi;
    }
}

// -------------------------------------------------------------------------
extern "C" void kernel_launch(void* const* d_in, const int* in_sizes, int n_in,
                              void* d_out, int out_size)
{
    const float* mixture = (const float*)d_in[0];
    const float* target  = (const float*)d_in[1];
    const float* noise   = (const float*)d_in[2];
    const int*   ref     = (const int*)d_in[3];
    float* out = (float*)d_out;

    dim3 b1(128, 4);
    dim3 g1((F_DIM + 127) / 128, TSPLIT, N_DIM * 2);   // 5 x 7 x 8 = 280 blocks
    cov_partial_kernel<<<g1, b1>>>(target, noise);

    int groups = (NF + 31) / 32;
    solve_kernel<<<groups, 256>>>(ref);

    dim3 g3((F_DIM + 127) / 128, T_DIM / TPER, N_DIM);
    beamform_kernel<<<g3, 128>>>(mixture, out);
}